// round 8
// baseline (speedup 1.0000x reference)
#include <cuda_runtime.h>
#include <cuda_bf16.h>
#include <math_constants.h>

// Problem constants
#define BATCH 8
#define C_IN  512
#define C_OUT 512
#define C_KEY 256
#define NTOK  2048

// ---------------------------------------------------------------------------
// Scratch (no cudaMalloc allowed): __device__ globals
// ---------------------------------------------------------------------------
__device__ float g_q[BATCH * C_KEY * NTOK];   // [b, c, n]  16.8 MB
__device__ float g_k[BATCH * C_KEY * NTOK];   // [b, c, n]  16.8 MB
__device__ float g_v[BATCH * C_OUT * NTOK];   // [b, c, n]  33.6 MB
__device__ float g_s[BATCH * NTOK * NTOK];    // [b, i, j] 134.2 MB (sim -> attn in place)

// ---------------------------------------------------------------------------
// Generic tiled SGEMM:  C[m,n] (+)= sum_k A(m,k) * B(k,n)
//   AT=false : A stored A[m*lda + k]   (row-major)
//   AT=true  : A stored A[k*lda + m]   (k-major / "transposed")
//   BT=false : B stored B[k*ldb + n]
//   BT=true  : B stored B[n*ldb + k]
// 128x128 block tile, BK=16, 256 threads, 8x8 per-thread micro-tile.
// All dims are exact multiples of the tile sizes for this problem -> no guards.
// ---------------------------------------------------------------------------
#define BM 128
#define BN 128
#define BKK 16
#define TM 8
#define TN 8
#define PAD 4

template <bool AT, bool BT>
__global__ __launch_bounds__(256, 2)
void sgemm_kernel(const float* __restrict__ A,
                  const float* __restrict__ B,
                  float* __restrict__ C,
                  int K, int lda, int ldb, int ldc,
                  long strideA, long strideB, long strideC)
{
    __shared__ __align__(16) float As[BKK][BM + PAD];
    __shared__ __align__(16) float Bs[BKK][BN + PAD];

    const int bz = blockIdx.z;
    A += (long)bz * strideA;
    B += (long)bz * strideB;
    C += (long)bz * strideC;

    const int m0 = blockIdx.y * BM;
    const int n0 = blockIdx.x * BN;
    const int t  = threadIdx.x;
    const int tx = t & 15;       // 0..15 -> column group
    const int ty = t >> 4;       // 0..15 -> row group

    float acc[TM][TN];
#pragma unroll
    for (int i = 0; i < TM; ++i)
#pragma unroll
        for (int j = 0; j < TN; ++j) acc[i][j] = 0.f;

    for (int k0 = 0; k0 < K; k0 += BKK) {
        // ---- load A tile into As[k][m] ----
        if (AT) {
#pragma unroll
            for (int i = 0; i < (BM * BKK) / 256; ++i) {
                int idx = t + i * 256;
                int m = idx & (BM - 1);
                int k = idx >> 7;            // idx / BM
                As[k][m] = A[(long)(k0 + k) * lda + (m0 + m)];
            }
        } else {
#pragma unroll
            for (int i = 0; i < (BM * BKK) / 256; ++i) {
                int idx = t + i * 256;
                int k = idx & (BKK - 1);
                int m = idx >> 4;            // idx / BKK
                As[k][m] = A[(long)(m0 + m) * lda + (k0 + k)];
            }
        }
        // ---- load B tile into Bs[k][n] ----
        if (!BT) {
#pragma unroll
            for (int i = 0; i < (BN * BKK) / 256; ++i) {
                int idx = t + i * 256;
                int n = idx & (BN - 1);
                int k = idx >> 7;
                Bs[k][n] = B[(long)(k0 + k) * ldb + (n0 + n)];
            }
        } else {
#pragma unroll
            for (int i = 0; i < (BN * BKK) / 256; ++i) {
                int idx = t + i * 256;
                int k = idx & (BKK - 1);
                int n = idx >> 4;
                Bs[k][n] = B[(long)(n0 + n) * ldb + (k0 + k)];
            }
        }
        __syncthreads();

        // ---- 8x8 outer-product micro kernel ----
#pragma unroll
        for (int k = 0; k < BKK; ++k) {
            float ar[TM], br[TN];
            *(float4*)&ar[0] = *(const float4*)&As[k][ty * TM];
            *(float4*)&ar[4] = *(const float4*)&As[k][ty * TM + 4];
            *(float4*)&br[0] = *(const float4*)&Bs[k][tx * TN];
            *(float4*)&br[4] = *(const float4*)&Bs[k][tx * TN + 4];
#pragma unroll
            for (int i = 0; i < TM; ++i)
#pragma unroll
                for (int j = 0; j < TN; ++j)
                    acc[i][j] += ar[i] * br[j];
        }
        __syncthreads();
    }

    // ---- store ----
#pragma unroll
    for (int i = 0; i < TM; ++i) {
        float* crow = C + (long)(m0 + ty * TM + i) * ldc + n0 + tx * TN;
        float4 v0 = make_float4(acc[i][0], acc[i][1], acc[i][2], acc[i][3]);
        float4 v1 = make_float4(acc[i][4], acc[i][5], acc[i][6], acc[i][7]);
        *(float4*)(crow)     = v0;
        *(float4*)(crow + 4) = v1;
    }
}

// ---------------------------------------------------------------------------
// Row softmax over S[b,i,:] (N=2048), in place. One block (256 thr) per row.
// ---------------------------------------------------------------------------
__global__ __launch_bounds__(256)
void softmax_kernel(float* __restrict__ S)
{
    float* row = S + (long)blockIdx.x * NTOK;
    const int t = threadIdx.x;

    float v[8];
    float mx = -CUDART_INF_F;
#pragma unroll
    for (int i = 0; i < 8; ++i) {
        v[i] = row[t + i * 256];
        mx = fmaxf(mx, v[i]);
    }
#pragma unroll
    for (int o = 16; o > 0; o >>= 1)
        mx = fmaxf(mx, __shfl_xor_sync(0xffffffffu, mx, o));

    __shared__ float red[8];
    if ((t & 31) == 0) red[t >> 5] = mx;
    __syncthreads();
    mx = red[0];
#pragma unroll
    for (int i = 1; i < 8; ++i) mx = fmaxf(mx, red[i]);

    float s = 0.f;
#pragma unroll
    for (int i = 0; i < 8; ++i) {
        v[i] = __expf(v[i] - mx);
        s += v[i];
    }
#pragma unroll
    for (int o = 16; o > 0; o >>= 1)
        s += __shfl_xor_sync(0xffffffffu, s, o);

    __syncthreads();   // everyone done reading red (max phase)
    if ((t & 31) == 0) red[t >> 5] = s;
    __syncthreads();
    s = 0.f;
#pragma unroll
    for (int i = 0; i < 8; ++i) s += red[i];

    const float inv = 1.f / s;
#pragma unroll
    for (int i = 0; i < 8; ++i)
        row[t + i * 256] = v[i] * inv;
}

// ---------------------------------------------------------------------------
// Launch
// ---------------------------------------------------------------------------
extern "C" void kernel_launch(void* const* d_in, const int* in_sizes, int n_in,
                              void* d_out, int out_size)
{
    // Map inputs by size (x, Wq, Wk, Wv in metadata order; Wq/Wk disambiguated
    // by first-seen order).
    const float* x  = nullptr;
    const float* Wq = nullptr;
    const float* Wk = nullptr;
    const float* Wv = nullptr;
    for (int i = 0; i < n_in; ++i) {
        const float* p = (const float*)d_in[i];
        if (in_sizes[i] == BATCH * C_IN * NTOK)      x = p;
        else if (in_sizes[i] == C_OUT * C_IN)        Wv = p;
        else if (in_sizes[i] == C_KEY * C_IN) {
            if (!Wq) Wq = p; else Wk = p;
        }
    }

    float *gq, *gk, *gv, *gs;
    cudaGetSymbolAddress((void**)&gq, g_q);
    cudaGetSymbolAddress((void**)&gk, g_k);
    cudaGetSymbolAddress((void**)&gv, g_v);
    cudaGetSymbolAddress((void**)&gs, g_s);

    float* out = (float*)d_out;
    dim3 blk(256);

    // 1) Projections:  C[o,n] = sum_c W[o,c] * x[b,c,n]
    //    A row-major (AT=false), B k-major (BT=false)
    sgemm_kernel<false, false><<<dim3(NTOK / BN, C_KEY / BM, BATCH), blk>>>(
        Wq, x, gq, C_IN, C_IN, NTOK, NTOK,
        0L, (long)C_IN * NTOK, (long)C_KEY * NTOK);
    sgemm_kernel<false, false><<<dim3(NTOK / BN, C_KEY / BM, BATCH), blk>>>(
        Wk, x, gk, C_IN, C_IN, NTOK, NTOK,
        0L, (long)C_IN * NTOK, (long)C_KEY * NTOK);
    sgemm_kernel<false, false><<<dim3(NTOK / BN, C_OUT / BM, BATCH), blk>>>(
        Wv, x, gv, C_IN, C_IN, NTOK, NTOK,
        0L, (long)C_IN * NTOK, (long)C_OUT * NTOK);

    // 2) sim: S[i,j] = sum_c K[c,i] * Q[c,j]
    //    A = K (k-major: A[k*lda+m], AT=true), B = Q (BT=false)
    sgemm_kernel<true, false><<<dim3(NTOK / BN, NTOK / BM, BATCH), blk>>>(
        gk, gq, gs, C_KEY, NTOK, NTOK, NTOK,
        (long)C_KEY * NTOK, (long)C_KEY * NTOK, (long)NTOK * NTOK);

    // 3) softmax over last axis of S (rows), in place
    softmax_kernel<<<BATCH * NTOK, blk>>>(gs);

    // 4) out[b,m,c] = sum_i P[i,m] * V[c,i]
    //    A = P (k-major over i: A[k*lda+m], AT=true)
    //    B = V (n-major over c: B[n*ldb+k], BT=true)
    sgemm_kernel<true, true><<<dim3(C_OUT / BN, NTOK / BM, BATCH), blk>>>(
        gs, gv, out, NTOK, NTOK, NTOK, C_OUT,
        (long)NTOK * NTOK, (long)C_OUT * NTOK, (long)NTOK * C_OUT);
}

// round 9
// speedup vs baseline: 1.0999x; 1.0999x over previous
#include <cuda_runtime.h>
#include <cuda_bf16.h>
#include <math_constants.h>

// Problem constants
#define BATCH 8
#define C_IN  512
#define C_OUT 512
#define C_KEY 256
#define NTOK  2048

// ---------------------------------------------------------------------------
// Scratch (no cudaMalloc allowed): __device__ globals
// ---------------------------------------------------------------------------
__device__ float g_q[BATCH * C_KEY * NTOK];   // [b, c, n]
__device__ float g_k[BATCH * C_KEY * NTOK];   // [b, c, n]
__device__ float g_v[BATCH * C_OUT * NTOK];   // [b, c, n]
__device__ float g_s[BATCH * NTOK * NTOK];    // [b, i, j] sim -> attn in place

// ---------------------------------------------------------------------------
// Packed fp32x2 helpers (FFMA2 — only reachable via PTX fma.rn.f32x2)
// ---------------------------------------------------------------------------
__device__ __forceinline__ void fma2(unsigned long long& d,
                                     unsigned long long a,
                                     unsigned long long b)
{
    asm("fma.rn.f32x2 %0, %1, %2, %0;" : "+l"(d) : "l"(a), "l"(b));
}

__device__ __forceinline__ unsigned long long dup2(float x)
{
    unsigned long long r;
    unsigned xi = __float_as_uint(x);
    asm("mov.b64 %0, {%1, %1};" : "=l"(r) : "r"(xi));
    return r;
}

// ---------------------------------------------------------------------------
// Tiled SGEMM with f32x2 packed accumulators + double-buffered SMEM.
//   C[m,n] = sum_k A(m,k) * B(k,n)
//   AT=false : A[m*lda + k]      AT=true : A[k*lda + m]
//   BT=false : B[k*ldb + n]      BT=true : B[n*ldb + k]
// 128x128 tile, BK=16, 256 threads, 8x8 micro-tile (acc packed pairwise on n).
// All dims exact multiples of tiles for this problem; all global float4 loads
// are 16B-aligned (lda/ldb in {512, 2048}, offsets multiples of 4).
// ---------------------------------------------------------------------------
#define BM 128
#define BN 128
#define BKK 16
#define TM 8
#define TN 8
#define PAD 4

template <bool AT, bool BT>
__global__ __launch_bounds__(256)
void sgemm2_kernel(const float* __restrict__ A,
                   const float* __restrict__ B,
                   float* __restrict__ C,
                   int K, int lda, int ldb, int ldc,
                   long strideA, long strideB, long strideC)
{
    __shared__ __align__(16) float As[2][BKK][BM + PAD];
    __shared__ __align__(16) float Bs[2][BKK][BN + PAD];

    const int bz = blockIdx.z;
    A += (long)bz * strideA;
    B += (long)bz * strideB;
    C += (long)bz * strideC;

    const int m0 = blockIdx.y * BM;
    const int n0 = blockIdx.x * BN;
    const int t  = threadIdx.x;
    const int tx = t & 15;       // n group
    const int ty = t >> 4;       // m group

    // load-index precompute
    const int lm4 = (t & 31) * 4;      // contiguous-minor loaders
    const int lkk = t >> 5;            // 0..7
    const int lr  = t >> 1;            // row for k-contiguous loaders
    const int lk8 = (t & 1) * 8;       // 0 or 8

    unsigned long long acc[TM][TN / 2];
#pragma unroll
    for (int i = 0; i < TM; ++i)
#pragma unroll
        for (int j = 0; j < TN / 2; ++j) acc[i][j] = 0ULL;

    float4 ra0, ra1, rb0, rb1;

    // ---- global loaders (to regs) ----
    auto ldgA = [&](int k0) {
        if (AT) {
            const float* p = A + (long)(k0 + lkk) * lda + m0 + lm4;
            ra0 = *(const float4*)p;
            ra1 = *(const float4*)(p + 8L * lda);
        } else {
            const float* p = A + (long)(m0 + lr) * lda + k0 + lk8;
            ra0 = *(const float4*)p;
            ra1 = *(const float4*)(p + 4);
        }
    };
    auto ldgB = [&](int k0) {
        if (!BT) {
            const float* p = B + (long)(k0 + lkk) * ldb + n0 + lm4;
            rb0 = *(const float4*)p;
            rb1 = *(const float4*)(p + 8L * ldb);
        } else {
            const float* p = B + (long)(n0 + lr) * ldb + k0 + lk8;
            rb0 = *(const float4*)p;
            rb1 = *(const float4*)(p + 4);
        }
    };
    // ---- smem stores (from regs) ----
    auto stsA = [&](int buf) {
        if (AT) {
            *(float4*)&As[buf][lkk][lm4]     = ra0;
            *(float4*)&As[buf][lkk + 8][lm4] = ra1;
        } else {
            As[buf][lk8 + 0][lr] = ra0.x; As[buf][lk8 + 1][lr] = ra0.y;
            As[buf][lk8 + 2][lr] = ra0.z; As[buf][lk8 + 3][lr] = ra0.w;
            As[buf][lk8 + 4][lr] = ra1.x; As[buf][lk8 + 5][lr] = ra1.y;
            As[buf][lk8 + 6][lr] = ra1.z; As[buf][lk8 + 7][lr] = ra1.w;
        }
    };
    auto stsB = [&](int buf) {
        if (!BT) {
            *(float4*)&Bs[buf][lkk][lm4]     = rb0;
            *(float4*)&Bs[buf][lkk + 8][lm4] = rb1;
        } else {
            Bs[buf][lk8 + 0][lr] = rb0.x; Bs[buf][lk8 + 1][lr] = rb0.y;
            Bs[buf][lk8 + 2][lr] = rb0.z; Bs[buf][lk8 + 3][lr] = rb0.w;
            Bs[buf][lk8 + 4][lr] = rb1.x; Bs[buf][lk8 + 5][lr] = rb1.y;
            Bs[buf][lk8 + 6][lr] = rb1.z; Bs[buf][lk8 + 7][lr] = rb1.w;
        }
    };

    const int nt = K / BKK;

    // prologue: tile 0 -> buf 0
    ldgA(0); ldgB(0);
    stsA(0); stsB(0);
    __syncthreads();

#pragma unroll 1
    for (int tt = 0; tt < nt; ++tt) {
        const int cur = tt & 1;

        if (tt + 1 < nt) { ldgA((tt + 1) * BKK); ldgB((tt + 1) * BKK); }

        // ---- compute on buf[cur] ----
#pragma unroll
        for (int k = 0; k < BKK; ++k) {
            float a_f[TM];
            *(float4*)&a_f[0] = *(const float4*)&As[cur][k][ty * TM];
            *(float4*)&a_f[4] = *(const float4*)&As[cur][k][ty * TM + 4];

            unsigned long long b2[TN / 2];
            {
                const ulonglong2* bp =
                    (const ulonglong2*)&Bs[cur][k][tx * TN];
                ulonglong2 q0 = bp[0];
                ulonglong2 q1 = bp[1];
                b2[0] = q0.x; b2[1] = q0.y; b2[2] = q1.x; b2[3] = q1.y;
            }
#pragma unroll
            for (int i = 0; i < TM; ++i) {
                unsigned long long a2 = dup2(a_f[i]);
#pragma unroll
                for (int j = 0; j < TN / 2; ++j)
                    fma2(acc[i][j], a2, b2[j]);
            }
        }

        if (tt + 1 < nt) {
            stsA(cur ^ 1);
            stsB(cur ^ 1);
            __syncthreads();
        }
    }

    // ---- epilogue: unpack + store ----
#pragma unroll
    for (int i = 0; i < TM; ++i) {
        float* crow = C + (long)(m0 + ty * TM + i) * ldc + n0 + tx * TN;
        float o[TN];
#pragma unroll
        for (int j = 0; j < TN / 2; ++j) {
            unsigned long long v = acc[i][j];
            o[2 * j]     = __uint_as_float((unsigned)(v & 0xffffffffu));
            o[2 * j + 1] = __uint_as_float((unsigned)(v >> 32));
        }
        *(float4*)(crow)     = make_float4(o[0], o[1], o[2], o[3]);
        *(float4*)(crow + 4) = make_float4(o[4], o[5], o[6], o[7]);
    }
}

// ---------------------------------------------------------------------------
// Row softmax over S[b,i,:] (N=2048), in place. One block (256 thr) per row.
// ---------------------------------------------------------------------------
__global__ __launch_bounds__(256)
void softmax_kernel(float* __restrict__ S)
{
    float* row = S + (long)blockIdx.x * NTOK;
    const int t = threadIdx.x;

    float v[8];
    float mx = -CUDART_INF_F;
#pragma unroll
    for (int i = 0; i < 8; ++i) {
        v[i] = row[t + i * 256];
        mx = fmaxf(mx, v[i]);
    }
#pragma unroll
    for (int o = 16; o > 0; o >>= 1)
        mx = fmaxf(mx, __shfl_xor_sync(0xffffffffu, mx, o));

    __shared__ float red[8];
    if ((t & 31) == 0) red[t >> 5] = mx;
    __syncthreads();
    mx = red[0];
#pragma unroll
    for (int i = 1; i < 8; ++i) mx = fmaxf(mx, red[i]);

    float s = 0.f;
#pragma unroll
    for (int i = 0; i < 8; ++i) {
        v[i] = __expf(v[i] - mx);
        s += v[i];
    }
#pragma unroll
    for (int o = 16; o > 0; o >>= 1)
        s += __shfl_xor_sync(0xffffffffu, s, o);

    __syncthreads();
    if ((t & 31) == 0) red[t >> 5] = s;
    __syncthreads();
    s = 0.f;
#pragma unroll
    for (int i = 0; i < 8; ++i) s += red[i];

    const float inv = 1.f / s;
#pragma unroll
    for (int i = 0; i < 8; ++i)
        row[t + i * 256] = v[i] * inv;
}

// ---------------------------------------------------------------------------
// Launch
// ---------------------------------------------------------------------------
extern "C" void kernel_launch(void* const* d_in, const int* in_sizes, int n_in,
                              void* d_out, int out_size)
{
    const float* x  = nullptr;
    const float* Wq = nullptr;
    const float* Wk = nullptr;
    const float* Wv = nullptr;
    for (int i = 0; i < n_in; ++i) {
        const float* p = (const float*)d_in[i];
        if (in_sizes[i] == BATCH * C_IN * NTOK)      x = p;
        else if (in_sizes[i] == C_OUT * C_IN)        Wv = p;
        else if (in_sizes[i] == C_KEY * C_IN) {
            if (!Wq) Wq = p; else Wk = p;
        }
    }

    float *gq, *gk, *gv, *gs;
    cudaGetSymbolAddress((void**)&gq, g_q);
    cudaGetSymbolAddress((void**)&gk, g_k);
    cudaGetSymbolAddress((void**)&gv, g_v);
    cudaGetSymbolAddress((void**)&gs, g_s);

    float* out = (float*)d_out;
    dim3 blk(256);

    // 1) Projections:  C[o,n] = sum_c W[o,c] * x[b,c,n]
    sgemm2_kernel<false, false><<<dim3(NTOK / BN, C_KEY / BM, BATCH), blk>>>(
        Wq, x, gq, C_IN, C_IN, NTOK, NTOK,
        0L, (long)C_IN * NTOK, (long)C_KEY * NTOK);
    sgemm2_kernel<false, false><<<dim3(NTOK / BN, C_KEY / BM, BATCH), blk>>>(
        Wk, x, gk, C_IN, C_IN, NTOK, NTOK,
        0L, (long)C_IN * NTOK, (long)C_KEY * NTOK);
    sgemm2_kernel<false, false><<<dim3(NTOK / BN, C_OUT / BM, BATCH), blk>>>(
        Wv, x, gv, C_IN, C_IN, NTOK, NTOK,
        0L, (long)C_IN * NTOK, (long)C_OUT * NTOK);

    // 2) sim: S[i,j] = sum_c K[c,i] * Q[c,j]
    sgemm2_kernel<true, false><<<dim3(NTOK / BN, NTOK / BM, BATCH), blk>>>(
        gk, gq, gs, C_KEY, NTOK, NTOK, NTOK,
        (long)C_KEY * NTOK, (long)C_KEY * NTOK, (long)NTOK * NTOK);

    // 3) softmax over rows of S, in place
    softmax_kernel<<<BATCH * NTOK, blk>>>(gs);

    // 4) out[b,m,c] = sum_i P[i,m] * V[c,i]
    sgemm2_kernel<true, true><<<dim3(C_OUT / BN, NTOK / BM, BATCH), blk>>>(
        gs, gv, out, NTOK, NTOK, NTOK, C_OUT,
        (long)NTOK * NTOK, (long)C_OUT * NTOK, (long)NTOK * C_OUT);
}

// round 10
// speedup vs baseline: 1.1671x; 1.0611x over previous
#include <cuda_runtime.h>
#include <cuda_bf16.h>
#include <math_constants.h>

// Problem constants
#define BATCH 8
#define C_IN  512
#define C_OUT 512
#define C_KEY 256
#define NTOK  2048

// ---------------------------------------------------------------------------
// Scratch (no cudaMalloc allowed): __device__ globals
// ---------------------------------------------------------------------------
__device__ float g_q[BATCH * C_KEY * NTOK];   // [b, c, n]
__device__ float g_k[BATCH * C_KEY * NTOK];   // [b, c, n]
__device__ float g_v[BATCH * C_OUT * NTOK];   // [b, c, n]
__device__ float g_s[BATCH * NTOK * NTOK];    // [b, i, j] sim -> attn in place

// ---------------------------------------------------------------------------
// Packed fp32x2 helpers (FFMA2 — only reachable via PTX fma.rn.f32x2)
// ---------------------------------------------------------------------------
__device__ __forceinline__ void fma2(unsigned long long& d,
                                     unsigned long long a,
                                     unsigned long long b)
{
    asm("fma.rn.f32x2 %0, %1, %2, %0;" : "+l"(d) : "l"(a), "l"(b));
}

__device__ __forceinline__ unsigned long long dup2(float x)
{
    unsigned long long r;
    unsigned xi = __float_as_uint(x);
    asm("mov.b64 %0, {%1, %1};" : "=l"(r) : "r"(xi));
    return r;
}

// ---------------------------------------------------------------------------
// Tiled SGEMM, f32x2 packed accumulators, single-buffered SMEM (R7 load path).
//   C[m,n] = sum_k A(m,k) * B(k,n)
//   AT=false : A[m*lda + k]      AT=true : A[k*lda + m]
//   BT=false : B[k*ldb + n]      BT=true : B[n*ldb + k]
// 128x128 tile, BK=16, 256 threads, 8x8 micro-tile (acc packed pairwise on n).
// All dims exact multiples of tiles; global accesses coalesced in all variants.
// ---------------------------------------------------------------------------
#define BM 128
#define BN 128
#define BKK 16
#define TM 8
#define TN 8
#define PAD 4

template <bool AT, bool BT>
__global__ __launch_bounds__(256, 2)
void sgemm2_kernel(const float* __restrict__ A,
                   const float* __restrict__ B,
                   float* __restrict__ C,
                   int K, int lda, int ldb, int ldc,
                   long strideA, long strideB, long strideC)
{
    __shared__ __align__(16) float As[BKK][BM + PAD];
    __shared__ __align__(16) float Bs[BKK][BN + PAD];

    const int bz = blockIdx.z;
    A += (long)bz * strideA;
    B += (long)bz * strideB;
    C += (long)bz * strideC;

    const int m0 = blockIdx.y * BM;
    const int n0 = blockIdx.x * BN;
    const int t  = threadIdx.x;
    const int tx = t & 15;       // n group
    const int ty = t >> 4;       // m group

    unsigned long long acc[TM][TN / 2];
#pragma unroll
    for (int i = 0; i < TM; ++i)
#pragma unroll
        for (int j = 0; j < TN / 2; ++j) acc[i][j] = 0ULL;

    for (int k0 = 0; k0 < K; k0 += BKK) {
        // ---- load A tile into As[k][m] (coalesced in both layouts) ----
        if (AT) {
#pragma unroll
            for (int i = 0; i < (BM * BKK) / 256; ++i) {
                int idx = t + i * 256;
                int m = idx & (BM - 1);
                int k = idx >> 7;
                As[k][m] = A[(long)(k0 + k) * lda + (m0 + m)];
            }
        } else {
#pragma unroll
            for (int i = 0; i < (BM * BKK) / 256; ++i) {
                int idx = t + i * 256;
                int k = idx & (BKK - 1);
                int m = idx >> 4;
                As[k][m] = A[(long)(m0 + m) * lda + (k0 + k)];
            }
        }
        // ---- load B tile into Bs[k][n] ----
        if (!BT) {
#pragma unroll
            for (int i = 0; i < (BN * BKK) / 256; ++i) {
                int idx = t + i * 256;
                int n = idx & (BN - 1);
                int k = idx >> 7;
                Bs[k][n] = B[(long)(k0 + k) * ldb + (n0 + n)];
            }
        } else {
#pragma unroll
            for (int i = 0; i < (BN * BKK) / 256; ++i) {
                int idx = t + i * 256;
                int k = idx & (BKK - 1);
                int n = idx >> 4;
                Bs[k][n] = B[(long)(n0 + n) * ldb + (k0 + k)];
            }
        }
        __syncthreads();

        // ---- f32x2 outer-product micro kernel ----
#pragma unroll
        for (int k = 0; k < BKK; ++k) {
            float a_f[TM];
            *(float4*)&a_f[0] = *(const float4*)&As[k][ty * TM];
            *(float4*)&a_f[4] = *(const float4*)&As[k][ty * TM + 4];

            unsigned long long b2[TN / 2];
            {
                const ulonglong2* bp = (const ulonglong2*)&Bs[k][tx * TN];
                ulonglong2 q0 = bp[0];
                ulonglong2 q1 = bp[1];
                b2[0] = q0.x; b2[1] = q0.y; b2[2] = q1.x; b2[3] = q1.y;
            }
#pragma unroll
            for (int i = 0; i < TM; ++i) {
                unsigned long long a2 = dup2(a_f[i]);
#pragma unroll
                for (int j = 0; j < TN / 2; ++j)
                    fma2(acc[i][j], a2, b2[j]);
            }
        }
        __syncthreads();
    }

    // ---- epilogue: unpack + store ----
#pragma unroll
    for (int i = 0; i < TM; ++i) {
        float* crow = C + (long)(m0 + ty * TM + i) * ldc + n0 + tx * TN;
        float o[TN];
#pragma unroll
        for (int j = 0; j < TN / 2; ++j) {
            unsigned long long v = acc[i][j];
            o[2 * j]     = __uint_as_float((unsigned)(v & 0xffffffffu));
            o[2 * j + 1] = __uint_as_float((unsigned)(v >> 32));
        }
        *(float4*)(crow)     = make_float4(o[0], o[1], o[2], o[3]);
        *(float4*)(crow + 4) = make_float4(o[4], o[5], o[6], o[7]);
    }
}

// ---------------------------------------------------------------------------
// Row softmax over S[b,i,:] (N=2048), in place. One block (256 thr) per row.
// ---------------------------------------------------------------------------
__global__ __launch_bounds__(256)
void softmax_kernel(float* __restrict__ S)
{
    float* row = S + (long)blockIdx.x * NTOK;
    const int t = threadIdx.x;

    float v[8];
    float mx = -CUDART_INF_F;
#pragma unroll
    for (int i = 0; i < 8; ++i) {
        v[i] = row[t + i * 256];
        mx = fmaxf(mx, v[i]);
    }
#pragma unroll
    for (int o = 16; o > 0; o >>= 1)
        mx = fmaxf(mx, __shfl_xor_sync(0xffffffffu, mx, o));

    __shared__ float red[8];
    if ((t & 31) == 0) red[t >> 5] = mx;
    __syncthreads();
    mx = red[0];
#pragma unroll
    for (int i = 1; i < 8; ++i) mx = fmaxf(mx, red[i]);

    float s = 0.f;
#pragma unroll
    for (int i = 0; i < 8; ++i) {
        v[i] = __expf(v[i] - mx);
        s += v[i];
    }
#pragma unroll
    for (int o = 16; o > 0; o >>= 1)
        s += __shfl_xor_sync(0xffffffffu, s, o);

    __syncthreads();
    if ((t & 31) == 0) red[t >> 5] = s;
    __syncthreads();
    s = 0.f;
#pragma unroll
    for (int i = 0; i < 8; ++i) s += red[i];

    const float inv = 1.f / s;
#pragma unroll
    for (int i = 0; i < 8; ++i)
        row[t + i * 256] = v[i] * inv;
}

// ---------------------------------------------------------------------------
// Launch
// ---------------------------------------------------------------------------
extern "C" void kernel_launch(void* const* d_in, const int* in_sizes, int n_in,
                              void* d_out, int out_size)
{
    const float* x  = nullptr;
    const float* Wq = nullptr;
    const float* Wk = nullptr;
    const float* Wv = nullptr;
    for (int i = 0; i < n_in; ++i) {
        const float* p = (const float*)d_in[i];
        if (in_sizes[i] == BATCH * C_IN * NTOK)      x = p;
        else if (in_sizes[i] == C_OUT * C_IN)        Wv = p;
        else if (in_sizes[i] == C_KEY * C_IN) {
            if (!Wq) Wq = p; else Wk = p;
        }
    }

    float *gq, *gk, *gv, *gs;
    cudaGetSymbolAddress((void**)&gq, g_q);
    cudaGetSymbolAddress((void**)&gk, g_k);
    cudaGetSymbolAddress((void**)&gv, g_v);
    cudaGetSymbolAddress((void**)&gs, g_s);

    float* out = (float*)d_out;
    dim3 blk(256);

    // 1) Projections:  C[o,n] = sum_c W[o,c] * x[b,c,n]
    sgemm2_kernel<false, false><<<dim3(NTOK / BN, C_KEY / BM, BATCH), blk>>>(
        Wq, x, gq, C_IN, C_IN, NTOK, NTOK,
        0L, (long)C_IN * NTOK, (long)C_KEY * NTOK);
    sgemm2_kernel<false, false><<<dim3(NTOK / BN, C_KEY / BM, BATCH), blk>>>(
        Wk, x, gk, C_IN, C_IN, NTOK, NTOK,
        0L, (long)C_IN * NTOK, (long)C_KEY * NTOK);
    sgemm2_kernel<false, false><<<dim3(NTOK / BN, C_OUT / BM, BATCH), blk>>>(
        Wv, x, gv, C_IN, C_IN, NTOK, NTOK,
        0L, (long)C_IN * NTOK, (long)C_OUT * NTOK);

    // 2) sim: S[i,j] = sum_c K[c,i] * Q[c,j]
    sgemm2_kernel<true, false><<<dim3(NTOK / BN, NTOK / BM, BATCH), blk>>>(
        gk, gq, gs, C_KEY, NTOK, NTOK, NTOK,
        (long)C_KEY * NTOK, (long)C_KEY * NTOK, (long)NTOK * NTOK);

    // 3) softmax over rows of S, in place
    softmax_kernel<<<BATCH * NTOK, blk>>>(gs);

    // 4) out[b,m,c] = sum_i P[i,m] * V[c,i]
    sgemm2_kernel<true, true><<<dim3(C_OUT / BN, NTOK / BM, BATCH), blk>>>(
        gs, gv, out, NTOK, NTOK, NTOK, C_OUT,
        (long)NTOK * NTOK, (long)C_OUT * NTOK, (long)NTOK * C_OUT);
}